// round 1
// baseline (speedup 1.0000x reference)
#include <cuda_runtime.h>

#define NN 100000
#define NE 1280000
#define FD 64
#define NG 1000
#define BN_EPS 1e-5f

// ---------------- device scratch (allocation-free rule: __device__ globals) ----
__device__ float g_dinv[NN];                 // degree -> rsqrt(degree)
__device__ float g_t[(size_t)NN * FD];       // transformed features (pre-message)
__device__ float g_agg[(size_t)NN * FD];     // aggregated features
__device__ float g_Wp[FD * FD];              // BN-folded weight
__device__ float g_crow[FD];                 // BN-folded row constant
__device__ float g_stats[6 * FD];            // s1 ss1 | s2 ss2 | s3 ss3
__device__ float g_gsum[NG * FD];            // per-graph sums
__device__ float g_gcnt[NG];                 // per-graph counts
__device__ float g_Woutp[FD * 2];            // BN3-folded output weight
__device__ float g_cb[2];                    // folded output bias
__device__ int   g_is64;                     // index dtype flag (detected from data)

// ---------------- dtype detection: int64 little-endian => odd 32-bit words all 0
__global__ void detect_kernel(const int* __restrict__ ei) {
    __shared__ int nz;
    if (threadIdx.x == 0) nz = 0;
    __syncthreads();
    int local = 0;
    for (int i = threadIdx.x; i < 4096; i += blockDim.x)
        if (ei[2 * i + 1] != 0) local = 1;
    if (local) nz = 1;
    __syncthreads();
    if (threadIdx.x == 0) g_is64 = (nz == 0) ? 1 : 0;
}

// ---------------- zero/seed accumulators (deg starts at 1.0 == self loop)
__global__ void init_kernel() {
    int i = blockIdx.x * blockDim.x + threadIdx.x;
    if (i < NN) g_dinv[i] = 1.0f;
    if (i < 6 * FD) g_stats[i] = 0.0f;
    if (i < NG * FD) g_gsum[i] = 0.0f;
    if (i < NG) g_gcnt[i] = 0.0f;
}

// ---------------- degree over edge targets
__global__ void deg_kernel(const int* __restrict__ ei) {
    int e = blockIdx.x * blockDim.x + threadIdx.x;
    if (e >= NE) return;
    int c = g_is64 ? ei[2 * (NE + e)] : ei[NE + e];
    atomicAdd(&g_dinv[c], 1.0f);
}

__global__ void rsqrt_kernel() {
    int i = blockIdx.x * blockDim.x + threadIdx.x;
    if (i < NN) g_dinv[i] = rsqrtf(g_dinv[i]);
}

// ---------------- per-feature sum / sumsq (optionally relu(in + bias))
__global__ void bn_stats_kernel(const float* __restrict__ xin, int use_agg,
                                const float* __restrict__ bias, int dorelu, int soff) {
    const float* __restrict__ src = use_agg ? g_agg : xin;
    int f   = threadIdx.x & 63;
    int sub = threadIdx.x >> 6;
    float bs = dorelu ? bias[f] : 0.0f;
    float s = 0.0f, ss = 0.0f;
    for (int n = blockIdx.x * 4 + sub; n < NN; n += gridDim.x * 4) {
        float v = src[(size_t)n * FD + f];
        if (dorelu) v = fmaxf(v + bs, 0.0f);
        s += v; ss += v * v;
    }
    atomicAdd(&g_stats[soff + f], s);
    atomicAdd(&g_stats[soff + 64 + f], ss);
}

// ---------------- fold BN(gamma,beta, stats) into W:  Wp = diag(a) W, crow = c @ W
__global__ void prep_kernel(const float* __restrict__ gg, const float* __restrict__ bb,
                            const float* __restrict__ W, int soff) {
    __shared__ float a[FD], c[FD];
    int f = threadIdx.x;
    float m = g_stats[soff + f] * (1.0f / NN);
    float v = fmaxf(g_stats[soff + 64 + f] * (1.0f / NN) - m * m, 0.0f);
    float af = gg[f] * rsqrtf(v + BN_EPS);
    a[f] = af;
    c[f] = bb[f] - m * af;
    __syncthreads();
    float cr = 0.0f;
    for (int i = 0; i < FD; i++) {
        float w = W[i * FD + f];
        g_Wp[i * FD + f] = a[i] * w;
        cr += c[i] * w;
    }
    g_crow[f] = cr;
}

// ---------------- t = prologue(in) @ Wp + crow  (prologue = relu(in + bias) if dorelu)
__global__ void gemm_kernel(const float* __restrict__ xin, int use_agg,
                            const float* __restrict__ bias, int dorelu) {
    __shared__ float sIn[16 * FD];
    __shared__ float sW[FD * FD];
    const float* __restrict__ src = use_agg ? g_agg : xin;
    int tid = threadIdx.x;
    for (int i = tid; i < FD * FD; i += 256) sW[i] = g_Wp[i];
    int base = blockIdx.x * 16;
    for (int i = tid; i < 16 * FD; i += 256) {
        int r = i >> 6, k = i & 63;
        float v = src[(size_t)(base + r) * FD + k];
        if (dorelu) v = fmaxf(v + bias[k], 0.0f);
        sIn[i] = v;
    }
    __syncthreads();
    int r = tid >> 4, tc = tid & 15;
    float4 acc = make_float4(0.f, 0.f, 0.f, 0.f);
    const float4* sW4 = (const float4*)sW;
#pragma unroll
    for (int k = 0; k < FD; k++) {
        float xv = sIn[r * FD + k];
        float4 w = sW4[k * 16 + tc];
        acc.x += xv * w.x; acc.y += xv * w.y; acc.z += xv * w.z; acc.w += xv * w.w;
    }
    float4 cr = ((const float4*)g_crow)[tc];
    acc.x += cr.x; acc.y += cr.y; acc.z += cr.z; acc.w += cr.w;
    ((float4*)g_t)[(size_t)(base + r) * 16 + tc] = acc;
}

// ---------------- self-loop term also initializes agg:  agg = t * dinv^2
__global__ void selfloop_kernel() {
    int i = blockIdx.x * blockDim.x + threadIdx.x;   // over NN*16 float4
    if (i >= NN * 16) return;
    int n = i >> 4;
    float d = g_dinv[n];
    float s = d * d;
    float4 v = ((const float4*)g_t)[i];
    v.x *= s; v.y *= s; v.z *= s; v.w *= s;
    ((float4*)g_agg)[i] = v;
}

// ---------------- edge scatter: warp per edge, lane = 2 features (coalesced atomics)
__global__ void scatter_kernel(const int* __restrict__ ei) {
    int lane   = threadIdx.x & 31;
    int warp   = (blockIdx.x * blockDim.x + threadIdx.x) >> 5;
    int nwarps = (gridDim.x * blockDim.x) >> 5;
    int is64 = g_is64;
    for (int e = warp; e < NE; e += nwarps) {
        int r, c;
        if (is64) { r = ei[2 * e]; c = ei[2 * (NE + e)]; }
        else      { r = ei[e];     c = ei[NE + e]; }
        float nrm = g_dinv[r] * g_dinv[c];
        float2 v = ((const float2*)g_t)[(size_t)r * 32 + lane];
        atomicAdd(&g_agg[(size_t)c * FD + 2 * lane],     v.x * nrm);
        atomicAdd(&g_agg[(size_t)c * FD + 2 * lane + 1], v.y * nrm);
    }
}

// ---------------- y = relu(agg + b2): global BN stats + per-graph sums/counts
__global__ void pool_kernel(const float* __restrict__ bias, const int* __restrict__ batch) {
    int f   = threadIdx.x & 63;
    int sub = threadIdx.x >> 6;
    int is64 = g_is64;
    float bs = bias[f];
    float s = 0.0f, ss = 0.0f;
    for (int n = blockIdx.x * 4 + sub; n < NN; n += gridDim.x * 4) {
        float v = fmaxf(g_agg[(size_t)n * FD + f] + bs, 0.0f);
        s += v; ss += v * v;
        int b = is64 ? batch[2 * n] : batch[n];
        atomicAdd(&g_gsum[b * FD + f], v);
        if (f == 0) atomicAdd(&g_gcnt[b], 1.0f);
    }
    atomicAdd(&g_stats[256 + f], s);
    atomicAdd(&g_stats[320 + f], ss);
}

// ---------------- fold BN3 into Wout:  Woutp = diag(a3) Wout, cb = c3 @ Wout + bout
__global__ void prep3_kernel(const float* __restrict__ gg, const float* __restrict__ bb,
                             const float* __restrict__ Wout, const float* __restrict__ bout) {
    __shared__ float c[FD];
    int f = threadIdx.x;
    float m = g_stats[256 + f] * (1.0f / NN);
    float v = fmaxf(g_stats[320 + f] * (1.0f / NN) - m * m, 0.0f);
    float af = gg[f] * rsqrtf(v + BN_EPS);
    c[f] = bb[f] - m * af;
    g_Woutp[f * 2]     = af * Wout[f * 2];
    g_Woutp[f * 2 + 1] = af * Wout[f * 2 + 1];
    __syncthreads();
    if (f < 2) {
        float acc = bout[f];
        for (int i = 0; i < FD; i++) acc += c[i] * Wout[i * 2 + f];
        g_cb[f] = acc;
    }
}

// ---------------- out[g] = (gsum[g]/max(cnt,1) .* a3 + c3) @ Wout + bout
__global__ void final_kernel(float* __restrict__ out, const float* __restrict__ bout) {
    int g = blockIdx.x * blockDim.x + threadIdx.x;
    if (g >= NG) return;
    float cnt = g_gcnt[g];
    if (cnt > 0.0f) {
        float inv = 1.0f / cnt;
        float a0 = g_cb[0], a1 = g_cb[1];
#pragma unroll 8
        for (int f = 0; f < FD; f++) {
            float p = g_gsum[g * FD + f] * inv;
            a0 += p * g_Woutp[f * 2];
            a1 += p * g_Woutp[f * 2 + 1];
        }
        out[g * 2] = a0; out[g * 2 + 1] = a1;
    } else {
        out[g * 2] = bout[0]; out[g * 2 + 1] = bout[1];
    }
}

extern "C" void kernel_launch(void* const* d_in, const int* in_sizes, int n_in,
                              void* d_out, int out_size) {
    const float* x       = (const float*)d_in[0];
    const int*   ei      = (const int*)d_in[1];   // int32 or int64 (detected)
    const int*   batch   = (const int*)d_in[2];
    const float* bn_in_g = (const float*)d_in[3];
    const float* bn_in_b = (const float*)d_in[4];
    const float* W1      = (const float*)d_in[5];
    const float* b1      = (const float*)d_in[6];
    const float* g1      = (const float*)d_in[7];
    const float* be1     = (const float*)d_in[8];
    const float* W2      = (const float*)d_in[9];
    const float* b2      = (const float*)d_in[10];
    const float* g2      = (const float*)d_in[11];
    const float* be2     = (const float*)d_in[12];
    const float* Wout    = (const float*)d_in[13];
    const float* bout    = (const float*)d_in[14];
    float* out = (float*)d_out;

    detect_kernel<<<1, 256>>>(ei);
    init_kernel<<<(NN + 255) / 256, 256>>>();
    deg_kernel<<<(NE + 255) / 256, 256>>>(ei);
    rsqrt_kernel<<<(NN + 255) / 256, 256>>>();

    // conv1: BN(x) folded into W1
    bn_stats_kernel<<<512, 256>>>(x, 0, x, 0, 0);
    prep_kernel<<<1, 64>>>(bn_in_g, bn_in_b, W1, 0);
    gemm_kernel<<<NN / 16, 256>>>(x, 0, x, 0);
    selfloop_kernel<<<(NN * 16 + 255) / 256, 256>>>();
    scatter_kernel<<<2048, 256>>>(ei);

    // conv2: BN(relu(agg1 + b1)) folded into W2
    bn_stats_kernel<<<512, 256>>>(x, 1, b1, 1, 128);
    prep_kernel<<<1, 64>>>(g1, be1, W2, 128);
    gemm_kernel<<<NN / 16, 256>>>(x, 1, b1, 1);
    selfloop_kernel<<<(NN * 16 + 255) / 256, 256>>>();
    scatter_kernel<<<2048, 256>>>(ei);

    // pool + BN3 folded into Wout
    pool_kernel<<<512, 256>>>(b2, batch);
    prep3_kernel<<<1, 64>>>(g2, be2, Wout, bout);
    final_kernel<<<4, 256>>>(out, bout);
}